// round 14
// baseline (speedup 1.0000x reference)
#include <cuda_runtime.h>
#include <cuda_fp16.h>
#include <mma.h>
#include <math.h>

using namespace nvcuda;

#define NN   50000
#define EE   1600000
#define FIN  512
#define HH   8
#define HID  64
#define NCLS 7
#define NEG_SLOPE 0.2f
#define NB   196            // (NN+255)/256

// ---------------- scratch (device globals) -----------------------------------
// All sync/counter state is self-restoring each call -> deterministic across
// graph replays without an init kernel.
__device__ int     g_cntR[NN], g_cntC[NN];
__device__ int     g_offR[NN + 1], g_offC[NN + 1];
__device__ int     g_curR[NN], g_curC[NN];
__device__ int     g_bsumR[256], g_bsumC[256], g_bprefR[256], g_bprefC[256];
__device__ int     g_ctr;
__device__ volatile int g_flag;
__device__ int     g_done;
__device__ int     g_sortedR[EE];   // edges sorted by col: stores row id
__device__ int     g_sortedC[EE];   // edges sorted by row: stores col id
__device__ __half2 g_xh_h [NN * 32];   // x @ W1, fp16
__device__ __half2 g_oute_h[NN * 32];  // hyperedge features, fp16
__device__ float   g_sird[NN * 16];    // interleaved (si, rden)
__device__ float   g_sj  [NN * HH];
__device__ float   g_Dinv[NN];
__device__ float   g_Binv[NN];
__device__ float   g_xh2 [NN * 8];     // h1 @ W2, padded 7->8
__device__ float   g_oute2[NN * 8];

__device__ __forceinline__ float lrelu(float a) { return a > 0.f ? a : NEG_SLOPE * a; }

// cp.async 16B with zero-fill predicate
__device__ __forceinline__ void cp16(void* s, const void* g, bool pred) {
    unsigned sa = (unsigned)__cvta_generic_to_shared(s);
    int sz = pred ? 16 : 0;
    asm volatile("cp.async.cg.shared.global [%0], [%1], 16, %2;"
                 :: "r"(sa), "l"(g), "r"(sz));
}
__device__ __forceinline__ void cp_commit() {
    asm volatile("cp.async.commit_group;");
}
// fire-and-forget global increment (no return -> no scoreboard wait)
__device__ __forceinline__ void red_add1(int* p) {
    asm volatile("red.global.add.u32 [%0], 1;" :: "l"(p) : "memory");
}

// ------- GEMM1 + fused degree count (count issued FIRST, fire-and-forget) ----
// stage = A 128x36 (pad) + B 32x68 (pad) = 6784 floats = 26.5KB; 2 stages = 53KB
#define GM_BM 128
#define GM_BK 32
#define LDA 36
#define LDB 68
#define LDC 68
#define STG 6784
__global__ void __launch_bounds__(256, 3)
k_gemm1(const float* __restrict__ X, const float* __restrict__ W,
        const float* __restrict__ att,
        const int* __restrict__ row, const int* __restrict__ col) {
    extern __shared__ float smem[];
    int tid = threadIdx.x;
    int warp = tid >> 5;
    int wm = warp >> 1;
    int wn = warp & 1;
    int bm = blockIdx.x * GM_BM;

    // prefetch stage 0 first (async, no dependency)
    {
        float* sA = &smem[0];
        float* sB = &smem[GM_BM * LDA];
#pragma unroll
        for (int l = 0; l < 4; l++) {
            int p = tid + l * 256, m = p >> 3, k4 = (p & 7) << 2;
            cp16(&sA[m * LDA + k4], &X[(size_t)(bm + m) * FIN + k4], (bm + m) < NN);
        }
#pragma unroll
        for (int l = 0; l < 2; l++) {
            int p = tid + l * 256, k = p >> 4, n4 = (p & 15) << 2;
            cp16(&sB[k * LDB + n4], &W[(size_t)k * 64 + n4], true);
        }
        cp_commit();
    }

    // fused degree count for this CTA's 4096-edge chunk, issued BEFORE the
    // main loop: load all indices, then fire REDs (drain during MMA loop).
    {
        int4 rr[4], cc[4];
        bool ok[4];
#pragma unroll
        for (int u = 0; u < 4; u++) {
            int e = blockIdx.x * 4096 + (tid + u * 256) * 4;
            ok[u] = (e < EE);
            if (ok[u]) {
                rr[u] = *(const int4*)&row[e];
                cc[u] = *(const int4*)&col[e];
            }
        }
#pragma unroll
        for (int u = 0; u < 4; u++) {
            if (ok[u]) {
                red_add1(&g_cntR[rr[u].x]);
                red_add1(&g_cntR[rr[u].y]);
                red_add1(&g_cntR[rr[u].z]);
                red_add1(&g_cntR[rr[u].w]);
                red_add1(&g_cntC[cc[u].x]);
                red_add1(&g_cntC[cc[u].y]);
                red_add1(&g_cntC[cc[u].z]);
                red_add1(&g_cntC[cc[u].w]);
            }
        }
    }

    wmma::fragment<wmma::accumulator, 16, 16, 8, float> acc[2][2];
#pragma unroll
    for (int i = 0; i < 2; i++)
#pragma unroll
        for (int j = 0; j < 2; j++) wmma::fill_fragment(acc[i][j], 0.f);

    int buf = 0;
    for (int k0 = 0; k0 < FIN; k0 += GM_BK) {
        int knext = k0 + GM_BK;
        if (knext < FIN) {
            float* sA = &smem[(buf ^ 1) * STG];
            float* sB = &smem[(buf ^ 1) * STG + GM_BM * LDA];
#pragma unroll
            for (int l = 0; l < 4; l++) {
                int p = tid + l * 256, m = p >> 3, k4 = (p & 7) << 2;
                cp16(&sA[m * LDA + k4], &X[(size_t)(bm + m) * FIN + knext + k4],
                     (bm + m) < NN);
            }
#pragma unroll
            for (int l = 0; l < 2; l++) {
                int p = tid + l * 256, k = p >> 4, n4 = (p & 15) << 2;
                cp16(&sB[k * LDB + n4], &W[(size_t)(knext + k) * 64 + n4], true);
            }
            cp_commit();
            asm volatile("cp.async.wait_group 1;");
        } else {
            asm volatile("cp.async.wait_group 0;");
        }
        __syncthreads();
        const float* sA = &smem[buf * STG];
        const float* sB = &smem[buf * STG + GM_BM * LDA];
#pragma unroll
        for (int kk = 0; kk < GM_BK; kk += 8) {
            wmma::fragment<wmma::matrix_a, 16, 16, 8, wmma::precision::tf32, wmma::row_major> a[2];
            wmma::fragment<wmma::matrix_b, 16, 16, 8, wmma::precision::tf32, wmma::row_major> b[2];
#pragma unroll
            for (int i = 0; i < 2; i++)
                wmma::load_matrix_sync(a[i], &sA[(wm * 32 + i * 16) * LDA + kk], LDA);
#pragma unroll
            for (int j = 0; j < 2; j++)
                wmma::load_matrix_sync(b[j], &sB[kk * LDB + wn * 32 + j * 16], LDB);
#pragma unroll
            for (int i = 0; i < 2; i++)
#pragma unroll
                for (int j = 0; j < 2; j++)
                    wmma::mma_sync(acc[i][j], a[i], b[j], acc[i][j]);
        }
        __syncthreads();
        buf ^= 1;
    }

    float* sC = smem;
#pragma unroll
    for (int i = 0; i < 2; i++)
#pragma unroll
        for (int j = 0; j < 2; j++)
            wmma::store_matrix_sync(&sC[(wm * 32 + i * 16) * LDC + wn * 32 + j * 16],
                                    acc[i][j], LDC, wmma::mem_row_major);
    __syncthreads();
#pragma unroll
    for (int l = 0; l < 4; l++) {
        int p = tid + l * 256;
        int m = p >> 3, h = p & 7;
        if (bm + m < NN) {
            const float* xr = &sC[m * LDC + h * 8];
            float si = 0.f, sj = 0.f;
#pragma unroll
            for (int c = 0; c < 8; c++) {
                float v = xr[c];
                si += v * __ldg(&att[h * 16 + c]);
                sj += v * __ldg(&att[h * 16 + 8 + c]);
            }
            g_sird[((bm + m) * 8 + h) * 2] = si;
            g_sj[(bm + m) * 8 + h] = sj;
        }
    }
#pragma unroll
    for (int l = 0; l < 16; l++) {
        int p = tid + l * 256;
        int m = p >> 5, f2 = p & 31;
        if (bm + m < NN)
            g_xh_h[(size_t)(bm + m) * 32 + f2] =
                __floats2half2_rn(sC[m * LDC + f2 * 2], sC[m * LDC + f2 * 2 + 1]);
    }
}

// -------- fused bsum + cross-block scan + scanfin (resident-grid spin) --------
__global__ void k_bsum_scanfin(const float* __restrict__ hw) {
    int t = threadIdx.x, b = blockIdx.x;
    int i = b * 256 + t;
    if (b == 0 && t == 0) { g_offR[NN] = EE; g_offC[NN] = EE; }
    int vr = (i < NN) ? g_cntR[i] : 0;
    int vc = (i < NN) ? g_cntC[i] : 0;

    // phase 1: per-block partial sums
    {
        int wr = vr, wc = vc;
        __shared__ int sr[8], sc[8];
#pragma unroll
        for (int o = 16; o; o >>= 1) {
            wr += __shfl_down_sync(~0u, wr, o);
            wc += __shfl_down_sync(~0u, wc, o);
        }
        if ((t & 31) == 0) { sr[t >> 5] = wr; sc[t >> 5] = wc; }
        __syncthreads();
        if (t < 8) {
            wr = sr[t]; wc = sc[t];
#pragma unroll
            for (int o = 4; o; o >>= 1) {
                wr += __shfl_down_sync(0xffu, wr, o);
                wc += __shfl_down_sync(0xffu, wc, o);
            }
            if (t == 0) { g_bsumR[b] = wr; g_bsumC[b] = wc; }
        }
    }
    __threadfence();
    __shared__ int s_last;
    if (t == 0) s_last = (atomicAdd(&g_ctr, 1) == gridDim.x - 1);
    __syncthreads();

    __shared__ int s[256];
    if (s_last) {
        int v = (t < NB) ? g_bsumR[t] : 0;
        s[t] = v; __syncthreads();
        for (int d = 1; d < 256; d <<= 1) {
            int x = (t >= d) ? s[t - d] : 0; __syncthreads();
            s[t] += x; __syncthreads();
        }
        g_bprefR[t] = s[t] - v;
        __syncthreads();
        int v2 = (t < NB) ? g_bsumC[t] : 0;
        s[t] = v2; __syncthreads();
        for (int d = 1; d < 256; d <<= 1) {
            int x = (t >= d) ? s[t - d] : 0; __syncthreads();
            s[t] += x; __syncthreads();
        }
        g_bprefC[t] = s[t] - v2;
        __threadfence();
        if (t == 0) g_flag = 1;
    }
    if (t == 0) { while (g_flag == 0) {} }
    __syncthreads();
    __threadfence();
    int bprefR = *((volatile int*)&g_bprefR[b]);
    int bprefC = *((volatile int*)&g_bprefC[b]);

    s[t] = vr; __syncthreads();
    for (int d = 1; d < 256; d <<= 1) {
        int x = (t >= d) ? s[t - d] : 0; __syncthreads();
        s[t] += x; __syncthreads();
    }
    if (i < NN) {
        int off = bprefR + s[t] - vr;
        g_offR[i] = off; g_curR[i] = off;
        g_cntR[i] = 0;                 // self-restore
    }
    __syncthreads();
    s[t] = vc; __syncthreads();
    for (int d = 1; d < 256; d <<= 1) {
        int x = (t >= d) ? s[t - d] : 0; __syncthreads();
        s[t] += x; __syncthreads();
    }
    if (i < NN) {
        int off = bprefC + s[t] - vc;
        g_offC[i] = off; g_curC[i] = off;
        g_Binv[i] = vc > 0 ? __ldg(&hw[i]) / (float)vc : 0.f;
        g_cntC[i] = 0;                 // self-restore
    }
    __syncthreads();
    if (t == 0) {
        int d = atomicAdd(&g_done, 1);
        if (d == gridDim.x - 1) { g_done = 0; g_ctr = 0; g_flag = 0; }
    }
}

__global__ void k_scatter(const int* __restrict__ row, const int* __restrict__ col) {
    int e = (blockIdx.x * blockDim.x + threadIdx.x) * 4;
    if (e >= EE) return;
    int4 r = *(const int4*)&row[e];
    int4 c = *(const int4*)&col[e];
    int p0 = atomicAdd(&g_curC[c.x], 1);
    int p1 = atomicAdd(&g_curC[c.y], 1);
    int p2 = atomicAdd(&g_curC[c.z], 1);
    int p3 = atomicAdd(&g_curC[c.w], 1);
    int q0 = atomicAdd(&g_curR[r.x], 1);
    int q1 = atomicAdd(&g_curR[r.y], 1);
    int q2 = atomicAdd(&g_curR[r.z], 1);
    int q3 = atomicAdd(&g_curR[r.w], 1);
    g_sortedR[p0] = r.x;
    g_sortedR[p1] = r.y;
    g_sortedR[p2] = r.z;
    g_sortedR[p3] = r.w;
    g_sortedC[q0] = c.x;
    g_sortedC[q1] = c.y;
    g_sortedC[q2] = c.z;
    g_sortedC[q3] = c.w;
}

// ---------------- denominator + Dinv (warp per node, by-row CSR) --------------
__global__ void k_den(const float* __restrict__ hw) {
    int w = (blockIdx.x * blockDim.x + threadIdx.x) >> 5;
    if (w >= NN) return;
    int lane = threadIdx.x & 31;
    int g = lane >> 3, h = lane & 7;
    int start = g_offR[w], end = g_offR[w + 1];
    float si_h = g_sird[(w * 8 + h) * 2];
    float den = 0.f, Dacc = 0.f;
    int i = start + g;
    for (; i + 4 < end; i += 8) {
        int c0 = g_sortedC[i];
        int c1 = g_sortedC[i + 4];
        float sj0 = __ldg(&g_sj[c0 * 8 + h]);
        float sj1 = __ldg(&g_sj[c1 * 8 + h]);
        den += __expf(lrelu(si_h + sj0)) + __expf(lrelu(si_h + sj1));
        if (h == 0) Dacc += __ldg(&hw[c0]) + __ldg(&hw[c1]);
    }
    if (i < end) {
        int c0 = g_sortedC[i];
        den += __expf(lrelu(si_h + __ldg(&g_sj[c0 * 8 + h])));
        if (h == 0) Dacc += __ldg(&hw[c0]);
    }
    den += __shfl_xor_sync(~0u, den, 8);
    den += __shfl_xor_sync(~0u, den, 16);
    Dacc += __shfl_xor_sync(~0u, Dacc, 8);
    Dacc += __shfl_xor_sync(~0u, Dacc, 16);
    if (g == 0) g_sird[(w * 8 + h) * 2 + 1] = 1.0f / (den + 1e-16f);
    if (lane == 0) g_Dinv[w] = Dacc > 0.f ? 1.0f / Dacc : 0.f;
}

// ---------------- prop1: nodes -> hyperedges (warp per hyperedge, fp16) -------
__global__ void k_prop1() {
    int w = (blockIdx.x * blockDim.x + threadIdx.x) >> 5;
    if (w >= NN) return;
    int lane = threadIdx.x & 31;
    int h = lane >> 2;
    int start = g_offC[w], end = g_offC[w + 1];
    float sj_h = g_sj[w * 8 + h];
    float binv = g_Binv[w];
    float ax = 0.f, ay = 0.f;
    int i = start;
    for (; i + 3 < end; i += 4) {
        int r0 = g_sortedR[i], r1 = g_sortedR[i + 1];
        int r2 = g_sortedR[i + 2], r3 = g_sortedR[i + 3];
        float2 sr0 = *(const float2*)&g_sird[(r0 * 8 + h) * 2];
        float2 sr1 = *(const float2*)&g_sird[(r1 * 8 + h) * 2];
        float2 sr2 = *(const float2*)&g_sird[(r2 * 8 + h) * 2];
        float2 sr3 = *(const float2*)&g_sird[(r3 * 8 + h) * 2];
        float2 f0 = __half22float2(g_xh_h[(size_t)r0 * 32 + lane]);
        float2 f1 = __half22float2(g_xh_h[(size_t)r1 * 32 + lane]);
        float2 f2 = __half22float2(g_xh_h[(size_t)r2 * 32 + lane]);
        float2 f3 = __half22float2(g_xh_h[(size_t)r3 * 32 + lane]);
        float w0 = __expf(lrelu(sr0.x + sj_h)) * sr0.y;
        float w1 = __expf(lrelu(sr1.x + sj_h)) * sr1.y;
        float w2 = __expf(lrelu(sr2.x + sj_h)) * sr2.y;
        float w3 = __expf(lrelu(sr3.x + sj_h)) * sr3.y;
        ax += w0 * f0.x + w1 * f1.x + w2 * f2.x + w3 * f3.x;
        ay += w0 * f0.y + w1 * f1.y + w2 * f2.y + w3 * f3.y;
    }
    for (; i < end; i++) {
        int r0 = g_sortedR[i];
        float2 sr0 = *(const float2*)&g_sird[(r0 * 8 + h) * 2];
        float2 f0 = __half22float2(g_xh_h[(size_t)r0 * 32 + lane]);
        float w0 = __expf(lrelu(sr0.x + sj_h)) * sr0.y;
        ax += w0 * f0.x; ay += w0 * f0.y;
    }
    g_oute_h[(size_t)w * 32 + lane] = __floats2half2_rn(ax * binv, ay * binv);
}

// ------- prop2 (fp16 gather) + bias + ELU + fused gemm2 (h1 never stored) -----
__global__ void k_prop2(const float* __restrict__ b1, const float* __restrict__ W2) {
    __shared__ float sW[448];
    for (int i = threadIdx.x; i < 448; i += 256) sW[i] = W2[i];
    __syncthreads();
    int w = (blockIdx.x * blockDim.x + threadIdx.x) >> 5;
    if (w >= NN) return;
    int lane = threadIdx.x & 31;
    int h = lane >> 2;
    int start = g_offR[w], end = g_offR[w + 1];
    float2 sr = *(const float2*)&g_sird[(w * 8 + h) * 2];
    float si_h = sr.x, rd_h = sr.y;
    float dinv = g_Dinv[w];
    float ax = 0.f, ay = 0.f;
    int i = start;
    for (; i + 3 < end; i += 4) {
        int c0 = g_sortedC[i], c1 = g_sortedC[i + 1];
        int c2 = g_sortedC[i + 2], c3 = g_sortedC[i + 3];
        float sj0 = __ldg(&g_sj[c0 * 8 + h]), sj1 = __ldg(&g_sj[c1 * 8 + h]);
        float sj2 = __ldg(&g_sj[c2 * 8 + h]), sj3 = __ldg(&g_sj[c3 * 8 + h]);
        float2 f0 = __half22float2(g_oute_h[(size_t)c0 * 32 + lane]);
        float2 f1 = __half22float2(g_oute_h[(size_t)c1 * 32 + lane]);
        float2 f2 = __half22float2(g_oute_h[(size_t)c2 * 32 + lane]);
        float2 f3 = __half22float2(g_oute_h[(size_t)c3 * 32 + lane]);
        float w0 = __expf(lrelu(si_h + sj0)) * rd_h;
        float w1 = __expf(lrelu(si_h + sj1)) * rd_h;
        float w2 = __expf(lrelu(si_h + sj2)) * rd_h;
        float w3 = __expf(lrelu(si_h + sj3)) * rd_h;
        ax += w0 * f0.x + w1 * f1.x + w2 * f2.x + w3 * f3.x;
        ay += w0 * f0.y + w1 * f1.y + w2 * f2.y + w3 * f3.y;
    }
    for (; i < end; i++) {
        int c0 = g_sortedC[i];
        float sj0 = __ldg(&g_sj[c0 * 8 + h]);
        float2 f0 = __half22float2(g_oute_h[(size_t)c0 * 32 + lane]);
        float w0 = __expf(lrelu(si_h + sj0)) * rd_h;
        ax += w0 * f0.x; ay += w0 * f0.y;
    }
    float vx = ax * dinv + __ldg(&b1[lane * 2]);
    float vy = ay * dinv + __ldg(&b1[lane * 2 + 1]);
    vx = vx > 0.f ? vx : expm1f(vx);
    vy = vy > 0.f ? vy : expm1f(vy);
    float a7[7];
#pragma unroll
    for (int j = 0; j < 7; j++)
        a7[j] = vx * sW[(lane * 2) * 7 + j] + vy * sW[(lane * 2 + 1) * 7 + j];
#pragma unroll
    for (int off = 16; off; off >>= 1)
#pragma unroll
        for (int j = 0; j < 7; j++)
            a7[j] += __shfl_xor_sync(~0u, a7[j], off);
    if (lane == 0) {
        float4* o = (float4*)&g_xh2[w * 8];
        o[0] = make_float4(a7[0], a7[1], a7[2], a7[3]);
        o[1] = make_float4(a7[4], a7[5], a7[6], 0.f);
    }
}

// ---------------- layer-2 propagation (warp per segment) ----------------------
__global__ void k2_prop1() {
    int w = (blockIdx.x * blockDim.x + threadIdx.x) >> 5;
    if (w >= NN) return;
    int lane = threadIdx.x & 31;
    int g = lane >> 3, j = lane & 7;
    int start = g_offC[w], end = g_offC[w + 1];
    float acc = 0.f;
    int i = start + g;
    for (; i + 4 < end; i += 8) {
        int r0 = g_sortedR[i], r1 = g_sortedR[i + 4];
        acc += __ldg(&g_xh2[r0 * 8 + j]) + __ldg(&g_xh2[r1 * 8 + j]);
    }
    if (i < end) acc += __ldg(&g_xh2[g_sortedR[i] * 8 + j]);
    acc += __shfl_xor_sync(~0u, acc, 8);
    acc += __shfl_xor_sync(~0u, acc, 16);
    if (g == 0) g_oute2[w * 8 + j] = acc * g_Binv[w];
}

// k2_prop2 + fused log_softmax
__global__ void k2_prop2(const float* __restrict__ b2, float* __restrict__ out) {
    int w = (blockIdx.x * blockDim.x + threadIdx.x) >> 5;
    if (w >= NN) return;
    int lane = threadIdx.x & 31;
    int g = lane >> 3, j = lane & 7;
    int start = g_offR[w], end = g_offR[w + 1];
    float acc = 0.f;
    int i = start + g;
    for (; i + 4 < end; i += 8) {
        int c0 = g_sortedC[i], c1 = g_sortedC[i + 4];
        acc += __ldg(&g_oute2[c0 * 8 + j]) + __ldg(&g_oute2[c1 * 8 + j]);
    }
    if (i < end) acc += __ldg(&g_oute2[g_sortedC[i] * 8 + j]);
    acc += __shfl_xor_sync(~0u, acc, 8);
    acc += __shfl_xor_sync(~0u, acc, 16);
    float v = (j < 7) ? acc * g_Dinv[w] + __ldg(&b2[j]) : -1e30f;
    float m = v;
#pragma unroll
    for (int off = 1; off < 8; off <<= 1)
        m = fmaxf(m, __shfl_xor_sync(~0u, m, off));
    float ex = (j < 7) ? __expf(v - m) : 0.f;
    float s = ex;
#pragma unroll
    for (int off = 1; off < 8; off <<= 1)
        s += __shfl_xor_sync(~0u, s, off);
    if (g == 0 && j < 7)
        out[(size_t)w * NCLS + j] = v - m - logf(s);
}

// ---------------- launch ------------------------------------------------------

extern "C" void kernel_launch(void* const* d_in, const int* in_sizes, int n_in,
                              void* d_out, int out_size) {
    const float* x   = (const float*)d_in[0];
    const int*   ei  = (const int*)  d_in[1];
    const float* hw  = (const float*)d_in[2];
    const float* W1  = (const float*)d_in[3];
    const float* att = (const float*)d_in[4];
    const float* b1  = (const float*)d_in[5];
    const float* W2  = (const float*)d_in[6];
    const float* b2  = (const float*)d_in[7];
    float* out = (float*)d_out;

    const int* row = ei;        // edge_index[0]
    const int* col = ei + EE;   // edge_index[1]

    const int EB4 = (EE / 4 + 255) / 256;     // 1563 (4 edges/thread)
    const int WB  = (NN * 32 + 255) / 256;    // 6250
    const int GEMM_SMEM = 2 * STG * 4;        // 54272 bytes

    cudaFuncSetAttribute(k_gemm1, cudaFuncAttributeMaxDynamicSharedMemorySize,
                         GEMM_SMEM);

    k_gemm1<<<(NN + GM_BM - 1) / GM_BM, 256, GEMM_SMEM>>>(x, W1, att, row, col);
    k_bsum_scanfin<<<NB, 256>>>(hw);
    k_scatter<<<EB4, 256>>>(row, col);
    k_gemm1_dummy_slot:;
    k_den<<<WB, 256>>>(hw);                   // launch #4 -> ncu
    k_prop1<<<WB, 256>>>();
    k_prop2<<<WB, 256>>>(b1, W2);
    k2_prop1<<<WB, 256>>>();
    k2_prop2<<<WB, 256>>>(b2, out);
}

// round 15
// speedup vs baseline: 1.1146x; 1.1146x over previous
#include <cuda_runtime.h>
#include <cuda_fp16.h>
#include <mma.h>
#include <math.h>

using namespace nvcuda;

#define NN   50000
#define EE   1600000
#define FIN  512
#define HH   8
#define HID  64
#define NCLS 7
#define NEG_SLOPE 0.2f
#define NB   196            // (NN+255)/256

// ---------------- scratch (device globals) -----------------------------------
// All sync/counter state is self-restoring each call -> deterministic across
// graph replays without an init kernel.
__device__ int     g_cntR[NN], g_cntC[NN];
__device__ int     g_offR[NN + 1], g_offC[NN + 1];
__device__ int     g_curR[NN], g_curC[NN];
__device__ int     g_bsumR[256], g_bsumC[256], g_bprefR[256], g_bprefC[256];
__device__ int     g_ctr;
__device__ volatile int g_flag;
__device__ int     g_done;
__device__ int     g_sortedR[EE];   // edges sorted by col: stores row id
__device__ int     g_sortedC[EE];   // edges sorted by row: stores col id
__device__ __half2 g_xh_h [NN * 32];   // x @ W1, fp16
__device__ __half2 g_oute_h[NN * 32];  // hyperedge features, fp16
__device__ float   g_sird[NN * 16];    // interleaved (si, rden)
__device__ float   g_sj  [NN * HH];
__device__ float   g_Dinv[NN];
__device__ float   g_Binv[NN];
__device__ float   g_xh2 [NN * 8];     // h1 @ W2, padded 7->8
__device__ float   g_oute2[NN * 8];

__device__ __forceinline__ float lrelu(float a) { return a > 0.f ? a : NEG_SLOPE * a; }

// cp.async 16B with zero-fill predicate
__device__ __forceinline__ void cp16(void* s, const void* g, bool pred) {
    unsigned sa = (unsigned)__cvta_generic_to_shared(s);
    int sz = pred ? 16 : 0;
    asm volatile("cp.async.cg.shared.global [%0], [%1], 16, %2;"
                 :: "r"(sa), "l"(g), "r"(sz));
}
__device__ __forceinline__ void cp_commit() {
    asm volatile("cp.async.commit_group;");
}

// ---------------- degree count (standalone; runs concurrent with gemm1) ------
__global__ void k_count(const int* __restrict__ row, const int* __restrict__ col) {
    int e = (blockIdx.x * blockDim.x + threadIdx.x) * 4;
    if (e >= EE) return;
    int4 r = *(const int4*)&row[e];
    int4 c = *(const int4*)&col[e];
    atomicAdd(&g_cntR[r.x], 1);
    atomicAdd(&g_cntR[r.y], 1);
    atomicAdd(&g_cntR[r.z], 1);
    atomicAdd(&g_cntR[r.w], 1);
    atomicAdd(&g_cntC[c.x], 1);
    atomicAdd(&g_cntC[c.y], 1);
    atomicAdd(&g_cntC[c.z], 1);
    atomicAdd(&g_cntC[c.w], 1);
}

// -------- fused bsum + cross-block scan + scanfin (resident-grid spin) --------
__global__ void k_bsum_scanfin(const float* __restrict__ hw) {
    int t = threadIdx.x, b = blockIdx.x;
    int i = b * 256 + t;
    if (b == 0 && t == 0) { g_offR[NN] = EE; g_offC[NN] = EE; }
    int vr = (i < NN) ? g_cntR[i] : 0;
    int vc = (i < NN) ? g_cntC[i] : 0;

    // phase 1: per-block partial sums
    {
        int wr = vr, wc = vc;
        __shared__ int sr[8], sc[8];
#pragma unroll
        for (int o = 16; o; o >>= 1) {
            wr += __shfl_down_sync(~0u, wr, o);
            wc += __shfl_down_sync(~0u, wc, o);
        }
        if ((t & 31) == 0) { sr[t >> 5] = wr; sc[t >> 5] = wc; }
        __syncthreads();
        if (t < 8) {
            wr = sr[t]; wc = sc[t];
#pragma unroll
            for (int o = 4; o; o >>= 1) {
                wr += __shfl_down_sync(0xffu, wr, o);
                wc += __shfl_down_sync(0xffu, wc, o);
            }
            if (t == 0) { g_bsumR[b] = wr; g_bsumC[b] = wc; }
        }
    }
    __threadfence();
    __shared__ int s_last;
    if (t == 0) s_last = (atomicAdd(&g_ctr, 1) == gridDim.x - 1);
    __syncthreads();

    __shared__ int s[256];
    if (s_last) {
        int v = (t < NB) ? g_bsumR[t] : 0;
        s[t] = v; __syncthreads();
        for (int d = 1; d < 256; d <<= 1) {
            int x = (t >= d) ? s[t - d] : 0; __syncthreads();
            s[t] += x; __syncthreads();
        }
        g_bprefR[t] = s[t] - v;
        __syncthreads();
        int v2 = (t < NB) ? g_bsumC[t] : 0;
        s[t] = v2; __syncthreads();
        for (int d = 1; d < 256; d <<= 1) {
            int x = (t >= d) ? s[t - d] : 0; __syncthreads();
            s[t] += x; __syncthreads();
        }
        g_bprefC[t] = s[t] - v2;
        __threadfence();
        if (t == 0) g_flag = 1;
    }
    if (t == 0) { while (g_flag == 0) {} }
    __syncthreads();
    __threadfence();
    int bprefR = *((volatile int*)&g_bprefR[b]);
    int bprefC = *((volatile int*)&g_bprefC[b]);

    s[t] = vr; __syncthreads();
    for (int d = 1; d < 256; d <<= 1) {
        int x = (t >= d) ? s[t - d] : 0; __syncthreads();
        s[t] += x; __syncthreads();
    }
    if (i < NN) {
        int off = bprefR + s[t] - vr;
        g_offR[i] = off; g_curR[i] = off;
        g_cntR[i] = 0;                 // self-restore
    }
    __syncthreads();
    s[t] = vc; __syncthreads();
    for (int d = 1; d < 256; d <<= 1) {
        int x = (t >= d) ? s[t - d] : 0; __syncthreads();
        s[t] += x; __syncthreads();
    }
    if (i < NN) {
        int off = bprefC + s[t] - vc;
        g_offC[i] = off; g_curC[i] = off;
        g_Binv[i] = vc > 0 ? __ldg(&hw[i]) / (float)vc : 0.f;
        g_cntC[i] = 0;                 // self-restore
    }
    __syncthreads();
    if (t == 0) {
        int d = atomicAdd(&g_done, 1);
        if (d == gridDim.x - 1) { g_done = 0; g_ctr = 0; g_flag = 0; }
    }
}

__global__ void k_scatter(const int* __restrict__ row, const int* __restrict__ col) {
    int e = (blockIdx.x * blockDim.x + threadIdx.x) * 4;
    if (e >= EE) return;
    int4 r = *(const int4*)&row[e];
    int4 c = *(const int4*)&col[e];
    int p0 = atomicAdd(&g_curC[c.x], 1);
    int p1 = atomicAdd(&g_curC[c.y], 1);
    int p2 = atomicAdd(&g_curC[c.z], 1);
    int p3 = atomicAdd(&g_curC[c.w], 1);
    int q0 = atomicAdd(&g_curR[r.x], 1);
    int q1 = atomicAdd(&g_curR[r.y], 1);
    int q2 = atomicAdd(&g_curR[r.z], 1);
    int q3 = atomicAdd(&g_curR[r.w], 1);
    g_sortedR[p0] = r.x;
    g_sortedR[p1] = r.y;
    g_sortedR[p2] = r.z;
    g_sortedR[p3] = r.w;
    g_sortedC[q0] = c.x;
    g_sortedC[q1] = c.y;
    g_sortedC[q2] = c.z;
    g_sortedC[q3] = c.w;
}

// ------- GEMM1 (pure): tf32 wmma, 2-stage cp.async, padded smem, 3 CTAs/SM ---
#define GM_BM 128
#define GM_BK 32
#define LDA 36
#define LDB 68
#define LDC 68
#define STG 6784
__global__ void __launch_bounds__(256, 3)
k_gemm1(const float* __restrict__ X, const float* __restrict__ W,
        const float* __restrict__ att) {
    extern __shared__ float smem[];
    int tid = threadIdx.x;
    int warp = tid >> 5;
    int wm = warp >> 1;
    int wn = warp & 1;
    int bm = blockIdx.x * GM_BM;

    wmma::fragment<wmma::accumulator, 16, 16, 8, float> acc[2][2];
#pragma unroll
    for (int i = 0; i < 2; i++)
#pragma unroll
        for (int j = 0; j < 2; j++) wmma::fill_fragment(acc[i][j], 0.f);

    {
        float* sA = &smem[0];
        float* sB = &smem[GM_BM * LDA];
#pragma unroll
        for (int l = 0; l < 4; l++) {
            int p = tid + l * 256, m = p >> 3, k4 = (p & 7) << 2;
            cp16(&sA[m * LDA + k4], &X[(size_t)(bm + m) * FIN + k4], (bm + m) < NN);
        }
#pragma unroll
        for (int l = 0; l < 2; l++) {
            int p = tid + l * 256, k = p >> 4, n4 = (p & 15) << 2;
            cp16(&sB[k * LDB + n4], &W[(size_t)k * 64 + n4], true);
        }
        cp_commit();
    }

    int buf = 0;
    for (int k0 = 0; k0 < FIN; k0 += GM_BK) {
        int knext = k0 + GM_BK;
        if (knext < FIN) {
            float* sA = &smem[(buf ^ 1) * STG];
            float* sB = &smem[(buf ^ 1) * STG + GM_BM * LDA];
#pragma unroll
            for (int l = 0; l < 4; l++) {
                int p = tid + l * 256, m = p >> 3, k4 = (p & 7) << 2;
                cp16(&sA[m * LDA + k4], &X[(size_t)(bm + m) * FIN + knext + k4],
                     (bm + m) < NN);
            }
#pragma unroll
            for (int l = 0; l < 2; l++) {
                int p = tid + l * 256, k = p >> 4, n4 = (p & 15) << 2;
                cp16(&sB[k * LDB + n4], &W[(size_t)(knext + k) * 64 + n4], true);
            }
            cp_commit();
            asm volatile("cp.async.wait_group 1;");
        } else {
            asm volatile("cp.async.wait_group 0;");
        }
        __syncthreads();
        const float* sA = &smem[buf * STG];
        const float* sB = &smem[buf * STG + GM_BM * LDA];
#pragma unroll
        for (int kk = 0; kk < GM_BK; kk += 8) {
            wmma::fragment<wmma::matrix_a, 16, 16, 8, wmma::precision::tf32, wmma::row_major> a[2];
            wmma::fragment<wmma::matrix_b, 16, 16, 8, wmma::precision::tf32, wmma::row_major> b[2];
#pragma unroll
            for (int i = 0; i < 2; i++)
                wmma::load_matrix_sync(a[i], &sA[(wm * 32 + i * 16) * LDA + kk], LDA);
#pragma unroll
            for (int j = 0; j < 2; j++)
                wmma::load_matrix_sync(b[j], &sB[kk * LDB + wn * 32 + j * 16], LDB);
#pragma unroll
            for (int i = 0; i < 2; i++)
#pragma unroll
                for (int j = 0; j < 2; j++)
                    wmma::mma_sync(acc[i][j], a[i], b[j], acc[i][j]);
        }
        __syncthreads();
        buf ^= 1;
    }

    float* sC = smem;
#pragma unroll
    for (int i = 0; i < 2; i++)
#pragma unroll
        for (int j = 0; j < 2; j++)
            wmma::store_matrix_sync(&sC[(wm * 32 + i * 16) * LDC + wn * 32 + j * 16],
                                    acc[i][j], LDC, wmma::mem_row_major);
    __syncthreads();
#pragma unroll
    for (int l = 0; l < 4; l++) {
        int p = tid + l * 256;
        int m = p >> 3, h = p & 7;
        if (bm + m < NN) {
            const float* xr = &sC[m * LDC + h * 8];
            float si = 0.f, sj = 0.f;
#pragma unroll
            for (int c = 0; c < 8; c++) {
                float v = xr[c];
                si += v * __ldg(&att[h * 16 + c]);
                sj += v * __ldg(&att[h * 16 + 8 + c]);
            }
            g_sird[((bm + m) * 8 + h) * 2] = si;
            g_sj[(bm + m) * 8 + h] = sj;
        }
    }
#pragma unroll
    for (int l = 0; l < 16; l++) {
        int p = tid + l * 256;
        int m = p >> 5, f2 = p & 31;
        if (bm + m < NN)
            g_xh_h[(size_t)(bm + m) * 32 + f2] =
                __floats2half2_rn(sC[m * LDC + f2 * 2], sC[m * LDC + f2 * 2 + 1]);
    }
}

// ---------------- denominator + Dinv (warp per node, by-row CSR) --------------
__global__ void k_den(const float* __restrict__ hw) {
    int w = (blockIdx.x * blockDim.x + threadIdx.x) >> 5;
    if (w >= NN) return;
    int lane = threadIdx.x & 31;
    int g = lane >> 3, h = lane & 7;
    int start = g_offR[w], end = g_offR[w + 1];
    float si_h = g_sird[(w * 8 + h) * 2];
    float den = 0.f, Dacc = 0.f;
    int i = start + g;
    for (; i + 4 < end; i += 8) {
        int c0 = g_sortedC[i];
        int c1 = g_sortedC[i + 4];
        float sj0 = __ldg(&g_sj[c0 * 8 + h]);
        float sj1 = __ldg(&g_sj[c1 * 8 + h]);
        den += __expf(lrelu(si_h + sj0)) + __expf(lrelu(si_h + sj1));
        if (h == 0) Dacc += __ldg(&hw[c0]) + __ldg(&hw[c1]);
    }
    if (i < end) {
        int c0 = g_sortedC[i];
        den += __expf(lrelu(si_h + __ldg(&g_sj[c0 * 8 + h])));
        if (h == 0) Dacc += __ldg(&hw[c0]);
    }
    den += __shfl_xor_sync(~0u, den, 8);
    den += __shfl_xor_sync(~0u, den, 16);
    Dacc += __shfl_xor_sync(~0u, Dacc, 8);
    Dacc += __shfl_xor_sync(~0u, Dacc, 16);
    if (g == 0) g_sird[(w * 8 + h) * 2 + 1] = 1.0f / (den + 1e-16f);
    if (lane == 0) g_Dinv[w] = Dacc > 0.f ? 1.0f / Dacc : 0.f;
}

// ---------------- prop1: nodes -> hyperedges (warp per hyperedge, fp16) -------
__global__ void k_prop1() {
    int w = (blockIdx.x * blockDim.x + threadIdx.x) >> 5;
    if (w >= NN) return;
    int lane = threadIdx.x & 31;
    int h = lane >> 2;
    int start = g_offC[w], end = g_offC[w + 1];
    float sj_h = g_sj[w * 8 + h];
    float binv = g_Binv[w];
    float ax = 0.f, ay = 0.f;
    int i = start;
    for (; i + 3 < end; i += 4) {
        int r0 = g_sortedR[i], r1 = g_sortedR[i + 1];
        int r2 = g_sortedR[i + 2], r3 = g_sortedR[i + 3];
        float2 sr0 = *(const float2*)&g_sird[(r0 * 8 + h) * 2];
        float2 sr1 = *(const float2*)&g_sird[(r1 * 8 + h) * 2];
        float2 sr2 = *(const float2*)&g_sird[(r2 * 8 + h) * 2];
        float2 sr3 = *(const float2*)&g_sird[(r3 * 8 + h) * 2];
        float2 f0 = __half22float2(g_xh_h[(size_t)r0 * 32 + lane]);
        float2 f1 = __half22float2(g_xh_h[(size_t)r1 * 32 + lane]);
        float2 f2 = __half22float2(g_xh_h[(size_t)r2 * 32 + lane]);
        float2 f3 = __half22float2(g_xh_h[(size_t)r3 * 32 + lane]);
        float w0 = __expf(lrelu(sr0.x + sj_h)) * sr0.y;
        float w1 = __expf(lrelu(sr1.x + sj_h)) * sr1.y;
        float w2 = __expf(lrelu(sr2.x + sj_h)) * sr2.y;
        float w3 = __expf(lrelu(sr3.x + sj_h)) * sr3.y;
        ax += w0 * f0.x + w1 * f1.x + w2 * f2.x + w3 * f3.x;
        ay += w0 * f0.y + w1 * f1.y + w2 * f2.y + w3 * f3.y;
    }
    for (; i < end; i++) {
        int r0 = g_sortedR[i];
        float2 sr0 = *(const float2*)&g_sird[(r0 * 8 + h) * 2];
        float2 f0 = __half22float2(g_xh_h[(size_t)r0 * 32 + lane]);
        float w0 = __expf(lrelu(sr0.x + sj_h)) * sr0.y;
        ax += w0 * f0.x; ay += w0 * f0.y;
    }
    g_oute_h[(size_t)w * 32 + lane] = __floats2half2_rn(ax * binv, ay * binv);
}

// ------- prop2 (fp16 gather) + bias + ELU + fused gemm2 (h1 never stored) -----
__global__ void k_prop2(const float* __restrict__ b1, const float* __restrict__ W2) {
    __shared__ float sW[448];
    for (int i = threadIdx.x; i < 448; i += 256) sW[i] = W2[i];
    __syncthreads();
    int w = (blockIdx.x * blockDim.x + threadIdx.x) >> 5;
    if (w >= NN) return;
    int lane = threadIdx.x & 31;
    int h = lane >> 2;
    int start = g_offR[w], end = g_offR[w + 1];
    float2 sr = *(const float2*)&g_sird[(w * 8 + h) * 2];
    float si_h = sr.x, rd_h = sr.y;
    float dinv = g_Dinv[w];
    float ax = 0.f, ay = 0.f;
    int i = start;
    for (; i + 3 < end; i += 4) {
        int c0 = g_sortedC[i], c1 = g_sortedC[i + 1];
        int c2 = g_sortedC[i + 2], c3 = g_sortedC[i + 3];
        float sj0 = __ldg(&g_sj[c0 * 8 + h]), sj1 = __ldg(&g_sj[c1 * 8 + h]);
        float sj2 = __ldg(&g_sj[c2 * 8 + h]), sj3 = __ldg(&g_sj[c3 * 8 + h]);
        float2 f0 = __half22float2(g_oute_h[(size_t)c0 * 32 + lane]);
        float2 f1 = __half22float2(g_oute_h[(size_t)c1 * 32 + lane]);
        float2 f2 = __half22float2(g_oute_h[(size_t)c2 * 32 + lane]);
        float2 f3 = __half22float2(g_oute_h[(size_t)c3 * 32 + lane]);
        float w0 = __expf(lrelu(si_h + sj0)) * rd_h;
        float w1 = __expf(lrelu(si_h + sj1)) * rd_h;
        float w2 = __expf(lrelu(si_h + sj2)) * rd_h;
        float w3 = __expf(lrelu(si_h + sj3)) * rd_h;
        ax += w0 * f0.x + w1 * f1.x + w2 * f2.x + w3 * f3.x;
        ay += w0 * f0.y + w1 * f1.y + w2 * f2.y + w3 * f3.y;
    }
    for (; i < end; i++) {
        int c0 = g_sortedC[i];
        float sj0 = __ldg(&g_sj[c0 * 8 + h]);
        float2 f0 = __half22float2(g_oute_h[(size_t)c0 * 32 + lane]);
        float w0 = __expf(lrelu(si_h + sj0)) * rd_h;
        ax += w0 * f0.x; ay += w0 * f0.y;
    }
    float vx = ax * dinv + __ldg(&b1[lane * 2]);
    float vy = ay * dinv + __ldg(&b1[lane * 2 + 1]);
    vx = vx > 0.f ? vx : expm1f(vx);
    vy = vy > 0.f ? vy : expm1f(vy);
    float a7[7];
#pragma unroll
    for (int j = 0; j < 7; j++)
        a7[j] = vx * sW[(lane * 2) * 7 + j] + vy * sW[(lane * 2 + 1) * 7 + j];
#pragma unroll
    for (int off = 16; off; off >>= 1)
#pragma unroll
        for (int j = 0; j < 7; j++)
            a7[j] += __shfl_xor_sync(~0u, a7[j], off);
    if (lane == 0) {
        float4* o = (float4*)&g_xh2[w * 8];
        o[0] = make_float4(a7[0], a7[1], a7[2], a7[3]);
        o[1] = make_float4(a7[4], a7[5], a7[6], 0.f);
    }
}

// ---------------- layer-2 propagation (warp per segment) ----------------------
__global__ void k2_prop1() {
    int w = (blockIdx.x * blockDim.x + threadIdx.x) >> 5;
    if (w >= NN) return;
    int lane = threadIdx.x & 31;
    int g = lane >> 3, j = lane & 7;
    int start = g_offC[w], end = g_offC[w + 1];
    float acc = 0.f;
    int i = start + g;
    for (; i + 4 < end; i += 8) {
        int r0 = g_sortedR[i], r1 = g_sortedR[i + 4];
        acc += __ldg(&g_xh2[r0 * 8 + j]) + __ldg(&g_xh2[r1 * 8 + j]);
    }
    if (i < end) acc += __ldg(&g_xh2[g_sortedR[i] * 8 + j]);
    acc += __shfl_xor_sync(~0u, acc, 8);
    acc += __shfl_xor_sync(~0u, acc, 16);
    if (g == 0) g_oute2[w * 8 + j] = acc * g_Binv[w];
}

// k2_prop2 + fused log_softmax
__global__ void k2_prop2(const float* __restrict__ b2, float* __restrict__ out) {
    int w = (blockIdx.x * blockDim.x + threadIdx.x) >> 5;
    if (w >= NN) return;
    int lane = threadIdx.x & 31;
    int g = lane >> 3, j = lane & 7;
    int start = g_offR[w], end = g_offR[w + 1];
    float acc = 0.f;
    int i = start + g;
    for (; i + 4 < end; i += 8) {
        int c0 = g_sortedC[i], c1 = g_sortedC[i + 4];
        acc += __ldg(&g_oute2[c0 * 8 + j]) + __ldg(&g_oute2[c1 * 8 + j]);
    }
    if (i < end) acc += __ldg(&g_oute2[g_sortedC[i] * 8 + j]);
    acc += __shfl_xor_sync(~0u, acc, 8);
    acc += __shfl_xor_sync(~0u, acc, 16);
    float v = (j < 7) ? acc * g_Dinv[w] + __ldg(&b2[j]) : -1e30f;
    float m = v;
#pragma unroll
    for (int off = 1; off < 8; off <<= 1)
        m = fmaxf(m, __shfl_xor_sync(~0u, m, off));
    float ex = (j < 7) ? __expf(v - m) : 0.f;
    float s = ex;
#pragma unroll
    for (int off = 1; off < 8; off <<= 1)
        s += __shfl_xor_sync(~0u, s, off);
    if (g == 0 && j < 7)
        out[(size_t)w * NCLS + j] = v - m - logf(s);
}

// ---------------- launch (forked-stream graph) ---------------------------------

extern "C" void kernel_launch(void* const* d_in, const int* in_sizes, int n_in,
                              void* d_out, int out_size) {
    const float* x   = (const float*)d_in[0];
    const int*   ei  = (const int*)  d_in[1];
    const float* hw  = (const float*)d_in[2];
    const float* W1  = (const float*)d_in[3];
    const float* att = (const float*)d_in[4];
    const float* b1  = (const float*)d_in[5];
    const float* W2  = (const float*)d_in[6];
    const float* b2  = (const float*)d_in[7];
    float* out = (float*)d_out;

    const int* row = ei;        // edge_index[0]
    const int* col = ei + EE;   // edge_index[1]

    const int EB4 = (EE / 4 + 255) / 256;     // 1563 (4 edges/thread)
    const int WB  = (NN * 32 + 255) / 256;    // 6250
    const int GEMM_SMEM = 2 * STG * 4;        // 54272 bytes

    // one-time handle creation (first call is outside graph capture)
    static cudaStream_t s2 = nullptr;
    static cudaEvent_t evFork = nullptr, evJoin = nullptr;
    if (s2 == nullptr) {
        cudaStreamCreateWithFlags(&s2, cudaStreamNonBlocking);
        cudaEventCreateWithFlags(&evFork, cudaEventDisableTiming);
        cudaEventCreateWithFlags(&evJoin, cudaEventDisableTiming);
        cudaFuncSetAttribute(k_gemm1, cudaFuncAttributeMaxDynamicSharedMemorySize,
                             GEMM_SMEM);
    }

    // fork: gemm1 on s2 runs concurrently with the CSR-build chain on stream 0
    cudaEventRecord(evFork, 0);
    cudaStreamWaitEvent(s2, evFork, 0);
    k_gemm1<<<(NN + GM_BM - 1) / GM_BM, 256, GEMM_SMEM, s2>>>(x, W1, att);
    cudaEventRecord(evJoin, s2);

    k_count<<<EB4, 256>>>(row, col);
    k_bsum_scanfin<<<NB, 256>>>(hw);
    k_scatter<<<EB4, 256>>>(row, col);

    // join: den needs both gemm1 (si/sj) and the CSR arrays
    cudaStreamWaitEvent(0, evJoin, 0);
    k_den<<<WB, 256>>>(hw);
    k_prop1<<<WB, 256>>>();
    k_prop2<<<WB, 256>>>(b1, W2);
    k2_prop1<<<WB, 256>>>();
    k2_prop2<<<WB, 256>>>(b2, out);
}